// round 12
// baseline (speedup 1.0000x reference)
#include <cuda_runtime.h>
#include <cuda_bf16.h>
#include <cuda_fp16.h>
#include <cstdint>

// ===================== problem constants =====================
#define B_ROWS 4096
#define NROWS  8192          // 2B
#define D_DIM  1024
// exp(sim/0.5) = exp2(sim * 2*log2(e))
#define EX2_SCALE 2.8853900817779268f

#define NTILE   64           // 8192 / 128
#define NUPPER  (NTILE * (NTILE + 1) / 2)   // 2080 upper-triangle tiles
#define GRIDX   2072         // 7 * 296 slots: blocks 0..7 run two tiles

// ===================== scratch (device globals; no allocs) =====================
__device__ uint8_t g_Z8[(size_t)NROWS * D_DIM];   // normalized rows, e4m3
__device__ float g_rowsum[NROWS];
__device__ float g_pos[NROWS];

// ===================== helpers =====================
__device__ __forceinline__ uint32_t smem_to_u32(const void* smem_ptr) {
    uint32_t addr;
    asm("{ .reg .u64 tmp; cvta.to.shared.u64 tmp, %1; cvt.u32.u64 %0, tmp; }"
        : "=r"(addr) : "l"(smem_ptr));
    return addr;
}

__device__ __forceinline__ void cp16(uint32_t saddr, const void* gptr) {
    asm volatile("cp.async.cg.shared.global [%0], [%1], 16;\n"
                 :: "r"(saddr), "l"(gptr));
}

__device__ __forceinline__ void ldsm_x4(uint32_t& r0, uint32_t& r1,
                                        uint32_t& r2, uint32_t& r3,
                                        uint32_t addr) {
    asm volatile("ldmatrix.sync.aligned.m8n8.x4.shared.b16 {%0,%1,%2,%3}, [%4];"
                 : "=r"(r0), "=r"(r1), "=r"(r2), "=r"(r3) : "r"(addr));
}

// fp8 e4m3 MMA m16n8k32 with f16 accumulate.
__device__ __forceinline__ void mma16832_fp8_f16(uint32_t* d, const uint32_t* a,
                                                 const uint32_t* b) {
    asm volatile(
        "mma.sync.aligned.m16n8k32.row.col.f16.e4m3.e4m3.f16 "
        "{%0,%1}, {%2,%3,%4,%5}, {%6,%7}, {%0,%1};"
        : "+r"(d[0]), "+r"(d[1])
        : "r"(a[0]), "r"(a[1]), "r"(a[2]), "r"(a[3]), "r"(b[0]), "r"(b[1]));
}

// FFMA-only exp2 for |x| <= ~4 (no MUFU): magic-constant round, deg-5 poly.
__device__ __forceinline__ float fexp2(float x) {
    float t = x + 12582912.0f;           // 1.5 * 2^23 : RN to integer
    float n = t - 12582912.0f;
    float f = x - n;                     // [-0.5, 0.5]
    float p = fmaf(f, 0.0013333558f, 0.0096181298f);
    p = fmaf(f, p, 0.0555041087f);
    p = fmaf(f, p, 0.2402265069f);
    p = fmaf(f, p, 0.6931471806f);
    p = fmaf(f, p, 1.0f);
    uint32_t sb = (__float_as_uint(t) << 23) + 0x3F800000u;   // 2^n bits
    return p * __uint_as_float(sb);
}

// ===================== kernel 1: L2-normalize -> e4m3 (+ zero rowsum/out) ===
__global__ __launch_bounds__(256) void normalize_kernel(
    const float* __restrict__ p1, const float* __restrict__ p2,
    float* __restrict__ out) {
    const int r = blockIdx.x;
    const int tid = threadIdx.x;
    const float* src = (r < B_ROWS) ? (p1 + (size_t)r * D_DIM)
                                    : (p2 + (size_t)(r - B_ROWS) * D_DIM);
    float4 v = reinterpret_cast<const float4*>(src)[tid];
    float ss = v.x * v.x + v.y * v.y + v.z * v.z + v.w * v.w;
#pragma unroll
    for (int o = 16; o > 0; o >>= 1) ss += __shfl_xor_sync(0xffffffffu, ss, o);
    __shared__ float acc[8];
    if ((tid & 31) == 0) acc[tid >> 5] = ss;
    __syncthreads();
    float tot = acc[0] + acc[1] + acc[2] + acc[3] + acc[4] + acc[5] + acc[6] + acc[7];
    float inv = rsqrtf(tot);
    unsigned short lo, hi;   // cvt packs first src into the HIGH byte
    asm("cvt.rn.satfinite.e4m3x2.f32 %0, %1, %2;"
        : "=h"(lo) : "f"(v.y * inv), "f"(v.x * inv));
    asm("cvt.rn.satfinite.e4m3x2.f32 %0, %1, %2;"
        : "=h"(hi) : "f"(v.w * inv), "f"(v.z * inv));
    uint32_t packed = (uint32_t)lo | ((uint32_t)hi << 16);
    reinterpret_cast<uint32_t*>(g_Z8 + (size_t)r * D_DIM)[tid] = packed;
    if (tid == 0) g_rowsum[r] = 0.0f;
    if (r == 0 && tid == 1) out[0] = 0.0f;
}

// ===================== kernel 2: symmetric sim GEMM (fp8/f16acc) ============
// Upper-triangle tiles only (mt <= nt); off-diag tiles scatter to rows AND
// columns by symmetry. CTA 128x128, 8 warps 4(m) x 2(n), warp tile 32x64.
// K chunked at 64 fp8 (64B rows). Single __syncthreads per chunk; grid 2072
// with blocks 0..7 each running two tiles (kills the 8th tail wave).
#define KC       64            // fp8 elements per chunk
#define NCHUNK   16            // 1024 / 64
#define STAGES   4
#define STAGE_BYTES 16384      // A 128x64B + B 128x64B
#define SMEM_TOTAL (STAGES * STAGE_BYTES)   // 65536

__global__ __launch_bounds__(256, 2) void simgemm_kernel() {
    extern __shared__ char smem[];
    const uint32_t smem_base = smem_to_u32(smem);
    const int tid = threadIdx.x;
    const int wid = tid >> 5;
    const int lane = tid & 31;

    // ---- tile-invariant addressing ----
    const int rowL = tid >> 1;        // loader row 0..127
    const int s0 = (tid & 1) * 2;     // loader segs
    const int xorv = (rowL >> 1) & 3;
    const uint32_t sw0 = (uint32_t)((s0 ^ xorv) * 16);
    const uint32_t sw1 = (uint32_t)(((s0 + 1) ^ xorv) * 16);
    const uint32_t srowA = smem_base + rowL * 64;

    const int wm = wid & 3;           // warp tiling 4(m) x 2(n)
    const int wn = wid >> 2;

    uint32_t aAddr[2], bAddr[4];      // ldmatrix bases (kstep1 = addr ^ 32)
#pragma unroll
    for (int mi = 0; mi < 2; ++mi) {
        int row = wm * 32 + mi * 16 + (lane & 15);
        int seg = (lane >> 4) & 1;
        int sws = seg ^ ((row >> 1) & 3);
        aAddr[mi] = smem_base + row * 64 + sws * 16;
    }
#pragma unroll
    for (int f = 0; f < 4; ++f) {
        int nrow = wn * 64 + f * 16 + ((lane >> 4) << 3) + (lane & 7);
        int seg = (lane >> 3) & 1;
        int sws = seg ^ ((nrow >> 1) & 3);
        bAddr[f] = smem_base + 8192 + nrow * 64 + sws * 16;
    }

    const int grp = lane >> 2;        // epilogue indices
    const int tig = lane & 3;

#pragma unroll 1
    for (int tile = blockIdx.x; tile < NUPPER; tile += GRIDX) {
        // ---- tile id -> (mt, nt) in upper triangle, row-band order ----
        int rem = tile;
        int mt = 0;
        int rowlen = NTILE;
        while (rem >= rowlen) { rem -= rowlen; ++mt; --rowlen; }
        const int nt = mt + rem;
        const bool isDiag = (mt == nt);
        const bool isPos  = (nt - mt == 32);   // positives pair (j = i ^ 4096)

        const uint8_t* gA0 = g_Z8 + (size_t)(mt * 128 + rowL) * D_DIM + s0 * 16;
        const uint8_t* gB0 = g_Z8 + (size_t)(nt * 128 + rowL) * D_DIM + s0 * 16;

        uint32_t acc[2][8][2];
#pragma unroll
        for (int mi = 0; mi < 2; ++mi)
#pragma unroll
            for (int ni = 0; ni < 8; ++ni) {
                acc[mi][ni][0] = 0u; acc[mi][ni][1] = 0u;
            }

        // ---- prologue: stages 0..2 ----
#pragma unroll
        for (int c = 0; c < STAGES - 1; ++c) {
            uint32_t sb = srowA + c * STAGE_BYTES;
            cp16(sb + sw0, gA0 + c * KC);
            cp16(sb + sw1, gA0 + c * KC + 16);
            cp16(sb + 8192 + sw0, gB0 + c * KC);
            cp16(sb + 8192 + sw1, gB0 + c * KC + 16);
            asm volatile("cp.async.commit_group;");
        }

        // ---- mainloop: ONE sync per chunk ----
        // order: wait(stage c ready) -> sync -> compute(c) -> issue(c+3)+commit
        // commit #: stage c's group is commit #c; at top of iter c total
        // commits = 3+c, wait_group(2) completes through #c exactly.
#pragma unroll 1
        for (int c = 0; c < NCHUNK; ++c) {
            asm volatile("cp.async.wait_group %0;" :: "n"(2));
            __syncthreads();

            const uint32_t stOff = (uint32_t)((c & (STAGES - 1)) * STAGE_BYTES);
#pragma unroll
            for (int ks = 0; ks < 2; ++ks) {      // K=32 fp8 per MMA
                const uint32_t kx = ks ? 32u : 0u;
                uint32_t a[2][4];
#pragma unroll
                for (int mi = 0; mi < 2; ++mi)
                    ldsm_x4(a[mi][0], a[mi][1], a[mi][2], a[mi][3],
                            (aAddr[mi] + stOff) ^ kx);
                uint32_t b[8][2];
#pragma unroll
                for (int f = 0; f < 4; ++f) {
                    uint32_t r0, r1, r2, r3;
                    ldsm_x4(r0, r1, r2, r3, (bAddr[f] + stOff) ^ kx);
                    b[2 * f][0] = r0; b[2 * f][1] = r1;
                    b[2 * f + 1][0] = r2; b[2 * f + 1][1] = r3;
                }
#pragma unroll
                for (int mi = 0; mi < 2; ++mi)
#pragma unroll
                    for (int ni = 0; ni < 8; ++ni)
                        mma16832_fp8_f16(acc[mi][ni], a[mi], b[ni]);
            }

            {   // issue chunk c+3 into stage (c-1)&3: every warp passed the
                // sync above, hence finished reading that stage in iter c-1.
                int cl = c + STAGES - 1;
                if (cl < NCHUNK) {
                    uint32_t sb = srowA + (cl & (STAGES - 1)) * STAGE_BYTES;
                    cp16(sb + sw0, gA0 + (size_t)cl * KC);
                    cp16(sb + sw1, gA0 + (size_t)cl * KC + 16);
                    cp16(sb + 8192 + sw0, gB0 + (size_t)cl * KC);
                    cp16(sb + 8192 + sw1, gB0 + (size_t)cl * KC + 16);
                }
                asm volatile("cp.async.commit_group;");
            }
        }

        // ---- epilogue: exp2 + row sums (+ symmetric column sums) + pos ----
        const int gcb = nt * 128 + wn * 64 + tig * 2;

        float colp[8][2];
#pragma unroll
        for (int ni = 0; ni < 8; ++ni) { colp[ni][0] = 0.0f; colp[ni][1] = 0.0f; }

#pragma unroll
        for (int mi = 0; mi < 2; ++mi) {
#pragma unroll
            for (int half = 0; half < 2; ++half) {
                const int gr = mt * 128 + wm * 32 + mi * 16 + grp + 8 * half;
                const int poscol = gr ^ 4096;
                float r = 0.0f;
#pragma unroll
                for (int ni = 0; ni < 8; ++ni) {
                    __half2 h2 = *reinterpret_cast<__half2*>(&acc[mi][ni][half]);
                    float2 f2 = __half22float2(h2);
#pragma unroll
                    for (int j = 0; j < 2; ++j) {
                        float s = (j == 0) ? f2.x : f2.y;
                        int gc = gcb + ni * 8 + j;
                        float e = fexp2(s * EX2_SCALE);
                        if (isDiag && gr == gc) e = 0.0f;  // mask self-sim
                        r += e;
                        colp[ni][j] += e;
                        if (isPos && gc == poscol) {       // sim symmetric
                            g_pos[gr] = s;
                            g_pos[gc] = s;
                        }
                    }
                }
                r += __shfl_xor_sync(0xffffffffu, r, 1);
                r += __shfl_xor_sync(0xffffffffu, r, 2);
                if (tig == 0) atomicAdd(&g_rowsum[gr], r);
            }
        }

        if (!isDiag) {
#pragma unroll
            for (int ni = 0; ni < 8; ++ni)
#pragma unroll
                for (int j = 0; j < 2; ++j) {
                    float v = colp[ni][j];
                    v += __shfl_xor_sync(0xffffffffu, v, 4);
                    v += __shfl_xor_sync(0xffffffffu, v, 8);
                    v += __shfl_xor_sync(0xffffffffu, v, 16);
                    colp[ni][j] = v;
                }
            if (grp == 0) {
#pragma unroll
                for (int ni = 0; ni < 8; ++ni)
#pragma unroll
                    for (int j = 0; j < 2; ++j)
                        atomicAdd(&g_rowsum[gcb + ni * 8 + j], colp[ni][j]);
            }
        }
        __syncthreads();   // all warps out of epilogue before next prologue
    }
}

// ===================== kernel 3: final scalar reduce (parallel) ============
__global__ __launch_bounds__(256) void finalize_kernel(float* __restrict__ out) {
    const int tid = threadIdx.x;
    const int i = blockIdx.x * 256 + tid;        // 32 blocks x 256 = 8192
    float s = logf(g_rowsum[i]) - 2.0f * g_pos[i];   // log(denom) - pos/T
#pragma unroll
    for (int o = 16; o > 0; o >>= 1) s += __shfl_xor_sync(0xffffffffu, s, o);
    __shared__ float acc[8];
    if ((tid & 31) == 0) acc[tid >> 5] = s;
    __syncthreads();
    if (tid == 0) {
        float t = acc[0] + acc[1] + acc[2] + acc[3] + acc[4] + acc[5] + acc[6] + acc[7];
        atomicAdd(out, t * (1.0f / (float)NROWS));
    }
}

// ===================== launch =====================
extern "C" void kernel_launch(void* const* d_in, const int* in_sizes, int n_in,
                              void* d_out, int out_size) {
    const float* p1 = (const float*)d_in[0];
    const float* p2 = (const float*)d_in[1];
    float* out = (float*)d_out;

    static int smem_set = 0;
    if (!smem_set) {
        cudaFuncSetAttribute(simgemm_kernel,
                             cudaFuncAttributeMaxDynamicSharedMemorySize,
                             SMEM_TOTAL);
        smem_set = 1;
    }

    normalize_kernel<<<NROWS, 256>>>(p1, p2, out);
    simgemm_kernel<<<GRIDX, 256, SMEM_TOTAL>>>();
    finalize_kernel<<<32, 256>>>(out);
}

// round 15
// speedup vs baseline: 1.3056x; 1.3056x over previous
#include <cuda_runtime.h>
#include <cuda_bf16.h>
#include <cuda_fp16.h>
#include <cstdint>

// ===================== problem constants =====================
#define B_ROWS 4096
#define NROWS  8192          // 2B
#define D_DIM  1024
// exp(sim/0.5) = exp2(sim * 2*log2(e))
#define EX2_SCALE 2.8853900817779268f

#define NTILE   64           // 8192 / 128
#define NUPPER  (NTILE * (NTILE + 1) / 2)   // 2080 upper-triangle tiles

// ===================== scratch (device globals; no allocs) =====================
__device__ uint8_t g_Z8[(size_t)NROWS * D_DIM];   // normalized rows, e4m3
__device__ float g_rowsum[NROWS];
__device__ float g_pos[NROWS];

// ===================== helpers =====================
__device__ __forceinline__ uint32_t smem_to_u32(const void* smem_ptr) {
    uint32_t addr;
    asm("{ .reg .u64 tmp; cvta.to.shared.u64 tmp, %1; cvt.u32.u64 %0, tmp; }"
        : "=r"(addr) : "l"(smem_ptr));
    return addr;
}

__device__ __forceinline__ void cp16(uint32_t saddr, const void* gptr) {
    asm volatile("cp.async.cg.shared.global [%0], [%1], 16;\n"
                 :: "r"(saddr), "l"(gptr));
}

__device__ __forceinline__ void ldsm_x4(uint32_t& r0, uint32_t& r1,
                                        uint32_t& r2, uint32_t& r3,
                                        uint32_t addr) {
    asm volatile("ldmatrix.sync.aligned.m8n8.x4.shared.b16 {%0,%1,%2,%3}, [%4];"
                 : "=r"(r0), "=r"(r1), "=r"(r2), "=r"(r3) : "r"(addr));
}

// fp8 e4m3 MMA m16n8k32 with f16 accumulate.
__device__ __forceinline__ void mma16832_fp8_f16(uint32_t* d, const uint32_t* a,
                                                 const uint32_t* b) {
    asm volatile(
        "mma.sync.aligned.m16n8k32.row.col.f16.e4m3.e4m3.f16 "
        "{%0,%1}, {%2,%3,%4,%5}, {%6,%7}, {%0,%1};"
        : "+r"(d[0]), "+r"(d[1])
        : "r"(a[0]), "r"(a[1]), "r"(a[2]), "r"(a[3]), "r"(b[0]), "r"(b[1]));
}

// FFMA-only exp2 for |x| <= ~4 (no MUFU): magic-constant round, deg-5 poly.
__device__ __forceinline__ float fexp2(float x) {
    float t = x + 12582912.0f;           // 1.5 * 2^23 : RN to integer
    float n = t - 12582912.0f;
    float f = x - n;                     // [-0.5, 0.5]
    float p = fmaf(f, 0.0013333558f, 0.0096181298f);
    p = fmaf(f, p, 0.0555041087f);
    p = fmaf(f, p, 0.2402265069f);
    p = fmaf(f, p, 0.6931471806f);
    p = fmaf(f, p, 1.0f);
    uint32_t sb = (__float_as_uint(t) << 23) + 0x3F800000u;   // 2^n bits
    return p * __uint_as_float(sb);
}

// ===================== kernel 1: L2-normalize -> e4m3, warp-per-row =========
// 8 warps per block, one row per warp. No smem, no __syncthreads.
// Lane owns interleaved float4s (idx lane + 32k) -> coalesced loads/stores.
__global__ __launch_bounds__(256) void normalize_kernel(
    const float* __restrict__ p1, const float* __restrict__ p2,
    float* __restrict__ out) {
    const int wid = threadIdx.x >> 5;
    const int lane = threadIdx.x & 31;
    const int r = blockIdx.x * 8 + wid;
    const float* src = (r < B_ROWS) ? (p1 + (size_t)r * D_DIM)
                                    : (p2 + (size_t)(r - B_ROWS) * D_DIM);
    const float4* s4 = reinterpret_cast<const float4*>(src);
    float4 v[8];
#pragma unroll
    for (int k = 0; k < 8; ++k) v[k] = s4[lane + 32 * k];
    float ss = 0.0f;
#pragma unroll
    for (int k = 0; k < 8; ++k)
        ss += v[k].x * v[k].x + v[k].y * v[k].y
            + v[k].z * v[k].z + v[k].w * v[k].w;
#pragma unroll
    for (int o = 16; o > 0; o >>= 1) ss += __shfl_xor_sync(0xffffffffu, ss, o);
    const float inv = rsqrtf(ss);
    uint32_t* dst = reinterpret_cast<uint32_t*>(g_Z8 + (size_t)r * D_DIM);
#pragma unroll
    for (int k = 0; k < 8; ++k) {
        unsigned short lo, hi;   // cvt packs first src into the HIGH byte
        asm("cvt.rn.satfinite.e4m3x2.f32 %0, %1, %2;"
            : "=h"(lo) : "f"(v[k].y * inv), "f"(v[k].x * inv));
        asm("cvt.rn.satfinite.e4m3x2.f32 %0, %1, %2;"
            : "=h"(hi) : "f"(v[k].w * inv), "f"(v[k].z * inv));
        dst[lane + 32 * k] = (uint32_t)lo | ((uint32_t)hi << 16);
    }
    if (lane == 0) g_rowsum[r] = 0.0f;
    if (r == 0 && lane == 1) out[0] = 0.0f;
}

// ===================== kernel 2: symmetric sim GEMM (fp8/f16acc) ============
// R11-proven structure, UNCHANGED: upper-triangle tiles (mt <= nt); off-diag
// tiles scatter exp sums to rows AND columns by symmetry. CTA 128x128,
// 8 warps 4(m) x 2(n), warp tile 32x64. K chunked at 64 fp8 (64B rows),
// 4-stage cp.async pipeline, commit-before-wait, two syncs per chunk.
#define KC       64            // fp8 elements per chunk
#define NCHUNK   16            // 1024 / 64
#define STAGES   4
#define STAGE_BYTES 16384      // A 128x64B + B 128x64B
#define SMEM_TOTAL (STAGES * STAGE_BYTES)   // 65536

__global__ __launch_bounds__(256, 2) void simgemm_kernel() {
    extern __shared__ char smem[];
    const uint32_t smem_base = smem_to_u32(smem);
    const int tid = threadIdx.x;
    const int wid = tid >> 5;
    const int lane = tid & 31;

    // ---- linear tile id -> (mt, nt) in upper triangle, row-band order ----
    int rem = blockIdx.x;
    int mt = 0;
    int rowlen = NTILE;
    while (rem >= rowlen) { rem -= rowlen; ++mt; --rowlen; }
    const int nt = mt + rem;
    const bool isDiag = (mt == nt);
    const bool isPos  = (nt - mt == 32);   // positives block pair (j = i ^ 4096)

    // ------- loader addressing: thread owns row tid>>1, segs (tid&1)*2,+1 ----
    const int rowL = tid >> 1;
    const int s0 = (tid & 1) * 2;
    const int xorv = (rowL >> 1) & 3;
    const uint32_t sw0 = (uint32_t)((s0 ^ xorv) * 16);
    const uint32_t sw1 = (uint32_t)(((s0 + 1) ^ xorv) * 16);
    const uint8_t* gA0 = g_Z8 + (size_t)(mt * 128 + rowL) * D_DIM + s0 * 16;
    const uint8_t* gB0 = g_Z8 + (size_t)(nt * 128 + rowL) * D_DIM + s0 * 16;
    const uint32_t srowA = smem_base + rowL * 64;

    // f16x2 accumulators: [mi][ni][half] (half: rows r / r+8)
    uint32_t acc[2][8][2];
#pragma unroll
    for (int mi = 0; mi < 2; ++mi)
#pragma unroll
        for (int ni = 0; ni < 8; ++ni) {
            acc[mi][ni][0] = 0u; acc[mi][ni][1] = 0u;
        }

    // warp tiling: 4(m) x 2(n), warp tile 32x64
    const int wm = wid & 3;
    const int wn = wid >> 2;

    // ldmatrix addresses (kstep 0; kstep 1 = addr ^ 32)
    uint32_t aAddr[2], bAddr[4];
#pragma unroll
    for (int mi = 0; mi < 2; ++mi) {
        int row = wm * 32 + mi * 16 + (lane & 15);
        int seg = (lane >> 4) & 1;
        int sws = seg ^ ((row >> 1) & 3);
        aAddr[mi] = smem_base + row * 64 + sws * 16;
    }
#pragma unroll
    for (int f = 0; f < 4; ++f) {
        int nrow = wn * 64 + f * 16 + ((lane >> 4) << 3) + (lane & 7);
        int seg = (lane >> 3) & 1;
        int sws = seg ^ ((nrow >> 1) & 3);
        bAddr[f] = smem_base + 8192 + nrow * 64 + sws * 16;
    }

    // ------- pipeline -------
#pragma unroll
    for (int c = 0; c < STAGES - 1; ++c) {
        uint32_t sb = srowA + c * STAGE_BYTES;
        cp16(sb + sw0, gA0 + c * KC);
        cp16(sb + sw1, gA0 + c * KC + 16);
        cp16(sb + 8192 + sw0, gB0 + c * KC);
        cp16(sb + 8192 + sw1, gB0 + c * KC + 16);
        asm volatile("cp.async.commit_group;");
    }

#pragma unroll 1
    for (int c = 0; c < NCHUNK; ++c) {
        {
            int cl = c + STAGES - 1;
            if (cl < NCHUNK) {
                uint32_t sb = srowA + (cl & (STAGES - 1)) * STAGE_BYTES;
                cp16(sb + sw0, gA0 + (size_t)cl * KC);
                cp16(sb + sw1, gA0 + (size_t)cl * KC + 16);
                cp16(sb + 8192 + sw0, gB0 + (size_t)cl * KC);
                cp16(sb + 8192 + sw1, gB0 + (size_t)cl * KC + 16);
            }
            asm volatile("cp.async.commit_group;");
        }
        asm volatile("cp.async.wait_group %0;" :: "n"(STAGES - 1));
        __syncthreads();

        const uint32_t stOff = (uint32_t)((c & (STAGES - 1)) * STAGE_BYTES);
#pragma unroll
        for (int ks = 0; ks < 2; ++ks) {          // K=32 fp8 per MMA
            const uint32_t kx = ks ? 32u : 0u;
            uint32_t a[2][4];
#pragma unroll
            for (int mi = 0; mi < 2; ++mi)
                ldsm_x4(a[mi][0], a[mi][1], a[mi][2], a[mi][3],
                        (aAddr[mi] + stOff) ^ kx);
            uint32_t b[8][2];
#pragma unroll
            for (int f = 0; f < 4; ++f) {
                uint32_t r0, r1, r2, r3;
                ldsm_x4(r0, r1, r2, r3, (bAddr[f] + stOff) ^ kx);
                b[2 * f][0] = r0; b[2 * f][1] = r1;
                b[2 * f + 1][0] = r2; b[2 * f + 1][1] = r3;
            }
#pragma unroll
            for (int mi = 0; mi < 2; ++mi)
#pragma unroll
                for (int ni = 0; ni < 8; ++ni)
                    mma16832_fp8_f16(acc[mi][ni], a[mi], b[ni]);
        }
        __syncthreads();
    }

    // ------- epilogue: exp2 + row sums (+ symmetric column sums) + positives
    const int grp = lane >> 2;
    const int tig = lane & 3;
    const int gcb = nt * 128 + wn * 64 + tig * 2;

    float colp[8][2];
#pragma unroll
    for (int ni = 0; ni < 8; ++ni) { colp[ni][0] = 0.0f; colp[ni][1] = 0.0f; }

#pragma unroll
    for (int mi = 0; mi < 2; ++mi) {
#pragma unroll
        for (int half = 0; half < 2; ++half) {
            const int gr = mt * 128 + wm * 32 + mi * 16 + grp + 8 * half;
            const int poscol = gr ^ 4096;
            float r = 0.0f;
#pragma unroll
            for (int ni = 0; ni < 8; ++ni) {
                __half2 h2 = *reinterpret_cast<__half2*>(&acc[mi][ni][half]);
                float2 f2 = __half22float2(h2);
#pragma unroll
                for (int j = 0; j < 2; ++j) {
                    float s = (j == 0) ? f2.x : f2.y;
                    int gc = gcb + ni * 8 + j;
                    float e = fexp2(s * EX2_SCALE);
                    if (isDiag && gr == gc) e = 0.0f;   // mask self-similarity
                    r += e;
                    colp[ni][j] += e;
                    if (isPos && gc == poscol) {        // sim symmetric:
                        g_pos[gr] = s;                  //  covers row side
                        g_pos[gc] = s;                  //  and column side
                    }
                }
            }
            // reduce row sum across the 4 lanes sharing each row
            r += __shfl_xor_sync(0xffffffffu, r, 1);
            r += __shfl_xor_sync(0xffffffffu, r, 2);
            if (tig == 0) atomicAdd(&g_rowsum[gr], r);
        }
    }

    if (!isDiag) {
        // column sums: reduce across the 8 row-groups (lane bits 2..4)
#pragma unroll
        for (int ni = 0; ni < 8; ++ni)
#pragma unroll
            for (int j = 0; j < 2; ++j) {
                float v = colp[ni][j];
                v += __shfl_xor_sync(0xffffffffu, v, 4);
                v += __shfl_xor_sync(0xffffffffu, v, 8);
                v += __shfl_xor_sync(0xffffffffu, v, 16);
                colp[ni][j] = v;
            }
        if (grp == 0) {
#pragma unroll
            for (int ni = 0; ni < 8; ++ni)
#pragma unroll
                for (int j = 0; j < 2; ++j)
                    atomicAdd(&g_rowsum[gcb + ni * 8 + j], colp[ni][j]);
        }
    }
}

// ===================== kernel 3: final scalar reduce (parallel) ============
__global__ __launch_bounds__(256) void finalize_kernel(float* __restrict__ out) {
    const int tid = threadIdx.x;
    const int i = blockIdx.x * 256 + tid;        // 32 blocks x 256 = 8192
    float s = logf(g_rowsum[i]) - 2.0f * g_pos[i];   // log(denom) - pos/T
#pragma unroll
    for (int o = 16; o > 0; o >>= 1) s += __shfl_xor_sync(0xffffffffu, s, o);
    __shared__ float acc[8];
    if ((tid & 31) == 0) acc[tid >> 5] = s;
    __syncthreads();
    if (tid == 0) {
        float t = acc[0] + acc[1] + acc[2] + acc[3] + acc[4] + acc[5] + acc[6] + acc[7];
        atomicAdd(out, t * (1.0f / (float)NROWS));
    }
}

// ===================== launch =====================
extern "C" void kernel_launch(void* const* d_in, const int* in_sizes, int n_in,
                              void* d_out, int out_size) {
    const float* p1 = (const float*)d_in[0];
    const float* p2 = (const float*)d_in[1];
    float* out = (float*)d_out;

    static int smem_set = 0;
    if (!smem_set) {
        cudaFuncSetAttribute(simgemm_kernel,
                             cudaFuncAttributeMaxDynamicSharedMemorySize,
                             SMEM_TOTAL);
        smem_set = 1;
    }

    normalize_kernel<<<NROWS / 8, 256>>>(p1, p2, out);
    simgemm_kernel<<<NUPPER, 256, SMEM_TOTAL>>>();
    finalize_kernel<<<32, 256>>>(out);
}